// round 1
// baseline (speedup 1.0000x reference)
#include <cuda_runtime.h>

#define TILE 128
#define NTHREADS 256
#define WARPS 8
#define ROWS_PER_WARP (TILE / WARPS)   // 16
#define GROUPS (ROWS_PER_WARP / 4)     // 4
#define PI_F 3.14159265358979323846f
#define RSQRT2 0.70710678118654752440f

__global__ __launch_bounds__(NTHREADS) void qp_kernel(
    const float* __restrict__ x,       // [B,1024]
    const float* __restrict__ pre_w,   // [4,1024]
    const float* __restrict__ pre_b,   // [4]
    const float* __restrict__ qw,      // [1,4,3]
    const float* __restrict__ post_w,  // [1024,4]
    const float* __restrict__ post_b,  // [1024]
    float* __restrict__ out,           // [B,1024]
    int B)
{
    __shared__ float wsm[4][1024];     // pre_w, q-major
    __shared__ float psm[4][1024];     // post_w SoA: psm[q][j]
    __shared__ float pbsm[1024];       // post_b
    __shared__ float4 hsm[TILE];       // angles per row
    __shared__ float4 zsm[TILE];       // expectation values per row
    __shared__ float  usm[4][8];       // Rot gate matrices (uniform)
    __shared__ float  prebias[4];

    const int tid  = threadIdx.x;
    const int warp = tid >> 5;
    const int lane = tid & 31;
    const int tile0 = blockIdx.x * TILE;

    // ---------------- stage weights into SMEM ----------------
    for (int i = tid; i < 4096; i += NTHREADS)
        ((float*)wsm)[i] = pre_w[i];

    const float4* pwg4 = (const float4*)post_w;   // [1024] float4, (j, q=0..3)
    for (int j = tid; j < 1024; j += NTHREADS) {
        float4 v = pwg4[j];
        psm[0][j] = v.x; psm[1][j] = v.y; psm[2][j] = v.z; psm[3][j] = v.w;
        pbsm[j] = post_b[j];
    }
    if (tid < 4) {
        prebias[tid] = pre_b[tid];
        float phi = qw[tid * 3 + 0];
        float th  = qw[tid * 3 + 1];
        float om  = qw[tid * 3 + 2];
        float spo, cpo, spm, cpm, st, ct;
        sincosf(0.5f * (phi + om), &spo, &cpo);
        sincosf(0.5f * (phi - om), &spm, &cpm);
        sincosf(0.5f * th,         &st,  &ct);
        // U = [[e^{-i(phi+om)/2} c , -e^{+i(phi-om)/2} s],
        //      [e^{-i(phi-om)/2} s ,  e^{+i(phi+om)/2} c]]
        usm[tid][0] =  cpo * ct;  usm[tid][1] = -spo * ct;  // u00
        usm[tid][2] = -cpm * st;  usm[tid][3] = -spm * st;  // u01
        usm[tid][4] =  cpm * st;  usm[tid][5] = -spm * st;  // u10
        usm[tid][6] =  cpo * ct;  usm[tid][7] =  spo * ct;  // u11
    }
    __syncthreads();

    // ---------------- Phase 1: h = tanh(x @ pre_w^T + pre_b) * pi ----------
    #pragma unroll 1
    for (int g = 0; g < GROUPS; g++) {
        const int lr0 = warp * ROWS_PER_WARP + g * 4;   // local row base
        const int r0  = tile0 + lr0;
        if (r0 + 3 < B) {
            const float4* xr0 = (const float4*)(x + (size_t)r0 * 1024);
            float acc[4][4];
            #pragma unroll
            for (int r = 0; r < 4; r++)
                #pragma unroll
                for (int q = 0; q < 4; q++) acc[r][q] = 0.0f;

            #pragma unroll
            for (int it = 0; it < 8; it++) {
                const int idx = it * 32 + lane;
                float4 w0 = ((const float4*)wsm[0])[idx];
                float4 w1 = ((const float4*)wsm[1])[idx];
                float4 w2 = ((const float4*)wsm[2])[idx];
                float4 w3 = ((const float4*)wsm[3])[idx];
                #pragma unroll
                for (int r = 0; r < 4; r++) {
                    float4 xv = __ldcs(&xr0[(size_t)r * 256 + idx]);
                    acc[r][0] += xv.x*w0.x + xv.y*w0.y + xv.z*w0.z + xv.w*w0.w;
                    acc[r][1] += xv.x*w1.x + xv.y*w1.y + xv.z*w1.z + xv.w*w1.w;
                    acc[r][2] += xv.x*w2.x + xv.y*w2.y + xv.z*w2.z + xv.w*w2.w;
                    acc[r][3] += xv.x*w3.x + xv.y*w3.y + xv.z*w3.z + xv.w*w3.w;
                }
            }
            // butterfly reduce — every lane ends with full sums
            #pragma unroll
            for (int r = 0; r < 4; r++)
                #pragma unroll
                for (int q = 0; q < 4; q++)
                    #pragma unroll
                    for (int off = 16; off > 0; off >>= 1)
                        acc[r][q] += __shfl_xor_sync(0xffffffffu, acc[r][q], off);

            if (lane < 4) {
                float4 hv;
                hv.x = tanhf(acc[lane][0] + prebias[0]) * PI_F;
                hv.y = tanhf(acc[lane][1] + prebias[1]) * PI_F;
                hv.z = tanhf(acc[lane][2] + prebias[2]) * PI_F;
                hv.w = tanhf(acc[lane][3] + prebias[3]) * PI_F;
                hsm[lr0 + lane] = hv;
            }
        }
    }
    __syncthreads();

    // ---------------- Phase 2: 4-qubit circuit, thread-per-row ----------
    if (tid < TILE && (tile0 + tid) < B) {
        float4 hv = hsm[tid];
        float hq[4] = {hv.x, hv.y, hv.z, hv.w};

        // v_q = RZ(atan(f^2)) RY(atan(f)) H |0>
        float vr[4][2], vi[4][2];
        #pragma unroll
        for (int q = 0; q < 4; q++) {
            float f = hq[q];
            float sa, ca; sincosf(0.5f * atanf(f), &sa, &ca);
            float A  = (ca - sa) * RSQRT2;
            float Bv = (ca + sa) * RSQRT2;
            float sb, cb; sincosf(0.5f * atanf(f * f), &sb, &cb);
            vr[q][0] = A  * cb;  vi[q][0] = -A  * sb;
            vr[q][1] = Bv * cb;  vi[q][1] =  Bv * sb;
        }

        // product state: qubit q <-> index bit (3-q)
        float c2r[4], c2i[4];
        #pragma unroll
        for (int j = 0; j < 4; j++) {
            int b3 = (j >> 1) & 1, b2 = j & 1;
            c2r[j] = vr[0][b3]*vr[1][b2] - vi[0][b3]*vi[1][b2];
            c2i[j] = vr[0][b3]*vi[1][b2] + vi[0][b3]*vr[1][b2];
        }
        float c3r[8], c3i[8];
        #pragma unroll
        for (int j = 0; j < 8; j++) {
            int hi = j >> 1, b1 = j & 1;
            c3r[j] = c2r[hi]*vr[2][b1] - c2i[hi]*vi[2][b1];
            c3i[j] = c2r[hi]*vi[2][b1] + c2i[hi]*vr[2][b1];
        }
        float pr[16], pim[16];
        #pragma unroll
        for (int j = 0; j < 16; j++) {
            int hi = j >> 1, b0 = j & 1;
            pr[j]  = c3r[hi]*vr[3][b0] - c3i[hi]*vi[3][b0];
            pim[j] = c3r[hi]*vi[3][b0] + c3i[hi]*vr[3][b0];
        }

        // CNOT ring (4 CNOTs) composed into one gather permutation.
        // psi_new[j] = psi_old[p0(p1(p2(p3(j))))]
        float tr[16], ti[16];
        #pragma unroll
        for (int j = 0; j < 16; j++) {
            int xg = j;
            xg ^= (xg & 1) << 3;           // CNOT c=3,t=0
            xg ^= (xg >> 1) & 1;           // CNOT c=2,t=3
            xg ^= ((xg >> 2) & 1) << 1;    // CNOT c=1,t=2
            xg ^= ((xg >> 3) & 1) << 2;    // CNOT c=0,t=1
            tr[j] = pr[xg];
            ti[j] = pim[xg];
        }

        // Rot gates (uniform matrices from SMEM), wire q -> bit (3-q)
        #pragma unroll
        for (int q = 0; q < 4; q++) {
            const float u00r = usm[q][0], u00i = usm[q][1];
            const float u01r = usm[q][2], u01i = usm[q][3];
            const float u10r = usm[q][4], u10i = usm[q][5];
            const float u11r = usm[q][6], u11i = usm[q][7];
            const int mask = 8 >> q;
            #pragma unroll
            for (int j0 = 0; j0 < 16; j0++) {
                if (j0 & mask) continue;
                const int j1 = j0 | mask;
                float ar = tr[j0], ai = ti[j0];
                float br = tr[j1], bi = ti[j1];
                tr[j0] = u00r*ar - u00i*ai + u01r*br - u01i*bi;
                ti[j0] = u00r*ai + u00i*ar + u01r*bi + u01i*br;
                tr[j1] = u10r*ar - u10i*ai + u11r*br - u11i*bi;
                ti[j1] = u10r*ai + u10i*ar + u11r*bi + u11i*br;
            }
        }

        // z_q = sum_j |psi_j|^2 * (1 - 2*bit_{3-q}(j))
        float z0 = 0.f, z1 = 0.f, z2 = 0.f, z3 = 0.f;
        #pragma unroll
        for (int j = 0; j < 16; j++) {
            float p = tr[j]*tr[j] + ti[j]*ti[j];
            z0 += (j & 8) ? -p : p;
            z1 += (j & 4) ? -p : p;
            z2 += (j & 2) ? -p : p;
            z3 += (j & 1) ? -p : p;
        }
        zsm[tid] = make_float4(z0, z1, z2, z3);
    }
    __syncthreads();

    // ---------------- Phase 3: out = z @ post_w^T + post_b ----------
    #pragma unroll 1
    for (int g = 0; g < GROUPS; g++) {
        const int lr0 = warp * ROWS_PER_WARP + g * 4;
        const int r0  = tile0 + lr0;
        if (r0 + 3 < B) {
            float4 zv0 = zsm[lr0 + 0];
            float4 zv1 = zsm[lr0 + 1];
            float4 zv2 = zsm[lr0 + 2];
            float4 zv3 = zsm[lr0 + 3];
            float4* o0 = (float4*)(out + (size_t)r0 * 1024);
            #pragma unroll
            for (int jt = 0; jt < 8; jt++) {
                const int fi = jt * 32 + lane;
                float4 w0 = ((const float4*)psm[0])[fi];
                float4 w1 = ((const float4*)psm[1])[fi];
                float4 w2 = ((const float4*)psm[2])[fi];
                float4 w3 = ((const float4*)psm[3])[fi];
                float4 bb = ((const float4*)pbsm)[fi];
                float4 o;
                // row 0
                o.x = bb.x + zv0.x*w0.x + zv0.y*w1.x + zv0.z*w2.x + zv0.w*w3.x;
                o.y = bb.y + zv0.x*w0.y + zv0.y*w1.y + zv0.z*w2.y + zv0.w*w3.y;
                o.z = bb.z + zv0.x*w0.z + zv0.y*w1.z + zv0.z*w2.z + zv0.w*w3.z;
                o.w = bb.w + zv0.x*w0.w + zv0.y*w1.w + zv0.z*w2.w + zv0.w*w3.w;
                __stcs(&o0[fi], o);
                // row 1
                o.x = bb.x + zv1.x*w0.x + zv1.y*w1.x + zv1.z*w2.x + zv1.w*w3.x;
                o.y = bb.y + zv1.x*w0.y + zv1.y*w1.y + zv1.z*w2.y + zv1.w*w3.y;
                o.z = bb.z + zv1.x*w0.z + zv1.y*w1.z + zv1.z*w2.z + zv1.w*w3.z;
                o.w = bb.w + zv1.x*w0.w + zv1.y*w1.w + zv1.z*w2.w + zv1.w*w3.w;
                __stcs(&o0[256 + fi], o);
                // row 2
                o.x = bb.x + zv2.x*w0.x + zv2.y*w1.x + zv2.z*w2.x + zv2.w*w3.x;
                o.y = bb.y + zv2.x*w0.y + zv2.y*w1.y + zv2.z*w2.y + zv2.w*w3.y;
                o.z = bb.z + zv2.x*w0.z + zv2.y*w1.z + zv2.z*w2.z + zv2.w*w3.z;
                o.w = bb.w + zv2.x*w0.w + zv2.y*w1.w + zv2.z*w2.w + zv2.w*w3.w;
                __stcs(&o0[512 + fi], o);
                // row 3
                o.x = bb.x + zv3.x*w0.x + zv3.y*w1.x + zv3.z*w2.x + zv3.w*w3.x;
                o.y = bb.y + zv3.x*w0.y + zv3.y*w1.y + zv3.z*w2.y + zv3.w*w3.y;
                o.z = bb.z + zv3.x*w0.z + zv3.y*w1.z + zv3.z*w2.z + zv3.w*w3.z;
                o.w = bb.w + zv3.x*w0.w + zv3.y*w1.w + zv3.z*w2.w + zv3.w*w3.w;
                __stcs(&o0[768 + fi], o);
            }
        }
    }
}

extern "C" void kernel_launch(void* const* d_in, const int* in_sizes, int n_in,
                              void* d_out, int out_size) {
    const float* x      = (const float*)d_in[0];
    const float* pre_w  = (const float*)d_in[1];
    const float* pre_b  = (const float*)d_in[2];
    const float* qw     = (const float*)d_in[3];
    const float* post_w = (const float*)d_in[4];
    const float* post_b = (const float*)d_in[5];
    float* out = (float*)d_out;

    const int B = in_sizes[0] / 1024;
    const int blocks = (B + TILE - 1) / TILE;
    qp_kernel<<<blocks, NTHREADS>>>(x, pre_w, pre_b, qw, post_w, post_b, out, B);
}